// round 1
// baseline (speedup 1.0000x reference)
#include <cuda_runtime.h>
#include <math.h>

// Scratch (allocation-free rule: __device__ globals)
static __device__ float g_pool[4096 * 845];   // [B,5,13,13] pooled L1 output
static __device__ float g_l2[4096 * 405];     // [B,5,9,9]   L2 output

__device__ __forceinline__ float silu_f(float x) {
    return __fdividef(x, 1.0f + __expf(-x));
}

// Uniform cubic B-spline: 4 nonzero bases at padded tap base j (taps j..j+3).
__device__ __forceinline__ void bspline4(float x, int& j, bool& ok,
                                         float& b0, float& b1, float& b2, float& b3) {
    float t  = (x + 1.0f) * 2.5f;       // (x+1)/h, h = 2/G = 0.4
    float fj = floorf(t);
    j  = (int)fj + 3;                   // knot interval index in [0,10] when in range
    ok = (j >= 0) && (j <= 10);
    float u  = t - fj;
    float um = 1.0f - u;
    float u2 = u * u, u3 = u2 * u;
    b0 = um * um * um * (1.0f / 6.0f);
    b1 = (3.0f * u3 - 6.0f * u2 + 4.0f) * (1.0f / 6.0f);
    b2 = (-3.0f * u3 + 3.0f * u2 + 3.0f * u + 1.0f) * (1.0f / 6.0f);
    b3 = u3 * (1.0f / 6.0f);
}

// ---------------- Kernel 1: KANConv(k=3, Cin=1, O=5) + maxpool2, fused ----------------
// One block per image; thread t<169 computes one pooled position (4 conv positions).
__global__ void __launch_bounds__(256)
k1_conv_pool(const float* __restrict__ x, const float* __restrict__ wb1,
             const float* __restrict__ ws1) {
    __shared__ float img[784];
    __shared__ float wb[45];
    __shared__ float wsp[5 * 9 * 14];
    int b = blockIdx.x, tid = threadIdx.x;

    for (int i = tid; i < 784; i += 256) img[i] = x[b * 784 + i];
    if (tid < 45) wb[tid] = wb1[tid];
    for (int m = tid; m < 5 * 9 * 14; m += 256) {
        int row = m / 14, mm = m % 14;
        wsp[m] = (mm >= 3 && mm <= 10) ? ws1[row * 8 + (mm - 3)] : 0.0f;
    }
    __syncthreads();
    if (tid >= 169) return;
    int ph = tid / 13, pw = tid % 13;

    float best[5];
#pragma unroll
    for (int o = 0; o < 5; o++) best[o] = -3.0e38f;

#pragma unroll
    for (int dy = 0; dy < 2; dy++)
#pragma unroll
    for (int dx = 0; dx < 2; dx++) {
        int y = 2 * ph + dy, xx = 2 * pw + dx;
        float acc[5] = {0, 0, 0, 0, 0};
#pragma unroll
        for (int r0 = 0; r0 < 3; r0++)
#pragma unroll
        for (int c0 = 0; c0 < 3; c0++) {
            int f = r0 * 3 + c0;
            float px = img[(y + r0) * 28 + xx + c0];
            float s = silu_f(px);
#pragma unroll
            for (int o = 0; o < 5; o++) acc[o] += s * wb[o * 9 + f];
            int j; bool ok; float b0, b1, b2, b3;
            bspline4(px, j, ok, b0, b1, b2, b3);
            if (ok) {
#pragma unroll
                for (int o = 0; o < 5; o++) {
                    const float* w = &wsp[(o * 9 + f) * 14 + j];
                    acc[o] += b0 * w[0] + b1 * w[1] + b2 * w[2] + b3 * w[3];
                }
            }
        }
#pragma unroll
        for (int o = 0; o < 5; o++) best[o] = fmaxf(best[o], acc[o]);
    }
#pragma unroll
    for (int o = 0; o < 5; o++) g_pool[b * 845 + o * 169 + tid] = best[o];
}

// ---------------- Kernel 2: KANConv(k=5, Cin=5, O=5) ----------------
// 3 images per block (3*81 = 243 active threads of 256).
#define K2_IMGS 3
#define K2_SMEM_FLOATS (K2_IMGS * 845 + 625 + 8750)
__global__ void __launch_bounds__(256)
k2_conv(const float* __restrict__ wb2, const float* __restrict__ ws2, int B) {
    extern __shared__ float sm[];
    float* in  = sm;                      // 3*845
    float* wb  = sm + K2_IMGS * 845;      // 625
    float* wsp = wb + 625;                // 5*125*14 = 8750
    int b0 = blockIdx.x * K2_IMGS, tid = threadIdx.x;

    for (int m = tid; m < 625; m += 256) wb[m] = wb2[m];
    for (int m = tid; m < 8750; m += 256) {
        int row = m / 14, mm = m % 14;
        wsp[m] = (mm >= 3 && mm <= 10) ? ws2[row * 8 + (mm - 3)] : 0.0f;
    }
    int nimg = min(K2_IMGS, B - b0);
    for (int m = tid; m < nimg * 845; m += 256) in[m] = g_pool[b0 * 845 + m];
    __syncthreads();

    int li = tid / 81, pos = tid % 81;
    if (li >= nimg) return;
    int oy = pos / 9, ox = pos % 9;

    float acc[5] = {0, 0, 0, 0, 0};
    for (int c = 0; c < 5; c++) {
        const float* inc = &in[li * 845 + c * 169];
        for (int kh = 0; kh < 5; kh++) {
            const float* row = &inc[(oy + kh) * 13 + ox];
#pragma unroll
            for (int kw = 0; kw < 5; kw++) {
                int f = (c * 5 + kh) * 5 + kw;
                float px = row[kw];
                float s = silu_f(px);
#pragma unroll
                for (int o = 0; o < 5; o++) acc[o] += s * wb[o * 125 + f];
                int j; bool ok; float b0, b1, b2, b3;
                bspline4(px, j, ok, b0, b1, b2, b3);
                if (ok) {
#pragma unroll
                    for (int o = 0; o < 5; o++) {
                        const float* w = &wsp[(o * 125 + f) * 14 + j];
                        acc[o] += b0 * w[0] + b1 * w[1] + b2 * w[2] + b3 * w[3];
                    }
                }
            }
        }
    }
    int b = b0 + li;
#pragma unroll
    for (int o = 0; o < 5; o++) g_l2[b * 405 + o * 81 + pos] = acc[o];
}

// ---------------- Kernel 3: KANConv(k=3, Cin=5, O=2) + flatten + FC ----------------
// 8 images per block; phase 1 computes h[8*98] in smem, phase 2 does FC with
// fc_w staged in smem padded to stride 99 (bank-conflict-free across o).
#define K3_IMGS 8
#define K3_SMEM_FLOATS (K3_IMGS * 405 + K3_IMGS * 98 + 90 + 1260 + 200 * 99 + 200)
__global__ void __launch_bounds__(256)
k3_conv_fc(const float* __restrict__ wb3, const float* __restrict__ ws3,
           const float* __restrict__ fcw, const float* __restrict__ fcb,
           float* __restrict__ out, int B) {
    extern __shared__ float sm[];
    float* in3 = sm;                            // 8*405 = 3240
    float* h   = in3 + K3_IMGS * 405;           // 8*98  = 784
    float* wb  = h + K3_IMGS * 98;              // 90
    float* wsp = wb + 90;                       // 2*45*14 = 1260
    float* fw  = wsp + 1260;                    // 200*99  = 19800
    float* fb  = fw + 200 * 99;                 // 200
    int tid = threadIdx.x;
    int b0 = blockIdx.x * K3_IMGS;
    int nimg = min(K3_IMGS, B - b0);

    for (int m = tid; m < 90; m += 256) wb[m] = wb3[m];
    for (int m = tid; m < 1260; m += 256) {
        int row = m / 14, mm = m % 14;
        wsp[m] = (mm >= 3 && mm <= 10) ? ws3[row * 8 + (mm - 3)] : 0.0f;
    }
    for (int m = tid; m < 200 * 98; m += 256) {
        int o = m / 98, i = m % 98;
        fw[o * 99 + i] = fcw[m];
    }
    if (tid < 200) fb[tid] = fcb[tid];
    for (int m = tid; m < nimg * 405; m += 256) in3[m] = g_l2[b0 * 405 + m];
    __syncthreads();

    // Phase 1: layer-3 conv, one (image,pos) per task
    for (int task = tid; task < nimg * 49; task += 256) {
        int li = task / 49, pos = task % 49;
        int oy = pos / 7, ox = pos % 7;
        float acc0 = 0.0f, acc1 = 0.0f;
        for (int c = 0; c < 5; c++) {
#pragma unroll
            for (int kh = 0; kh < 3; kh++)
#pragma unroll
            for (int kw = 0; kw < 3; kw++) {
                int f = (c * 3 + kh) * 3 + kw;
                float px = in3[li * 405 + c * 81 + (oy + kh) * 9 + ox + kw];
                float s = silu_f(px);
                acc0 += s * wb[f];
                acc1 += s * wb[45 + f];
                int j; bool ok; float b0, b1, b2, b3;
                bspline4(px, j, ok, b0, b1, b2, b3);
                if (ok) {
                    const float* w0 = &wsp[f * 14 + j];
                    const float* w1 = &wsp[(45 + f) * 14 + j];
                    acc0 += b0 * w0[0] + b1 * w0[1] + b2 * w0[2] + b3 * w0[3];
                    acc1 += b0 * w1[0] + b1 * w1[1] + b2 * w1[2] + b3 * w1[3];
                }
            }
        }
        h[li * 98 + pos]      = acc0;   // flatten order: o*49 + y*7 + x
        h[li * 98 + 49 + pos] = acc1;
    }
    __syncthreads();

    // Phase 2: FC [98] -> [200] per image
    for (int task = tid; task < nimg * 200; task += 256) {
        int li = task / 200, o = task % 200;
        float acc = fb[o];
        const float* hr = &h[li * 98];
        const float* wr = &fw[o * 99];
#pragma unroll 7
        for (int i = 0; i < 98; i++) acc += hr[i] * wr[i];
        out[(b0 + li) * 200 + o] = acc;
    }
}

extern "C" void kernel_launch(void* const* d_in, const int* in_sizes, int n_in,
                              void* d_out, int out_size) {
    const float* x   = (const float*)d_in[0];
    const float* wb1 = (const float*)d_in[1];
    const float* ws1 = (const float*)d_in[2];
    const float* wb2 = (const float*)d_in[3];
    const float* ws2 = (const float*)d_in[4];
    const float* wb3 = (const float*)d_in[5];
    const float* ws3 = (const float*)d_in[6];
    const float* fcw = (const float*)d_in[7];
    const float* fcb = (const float*)d_in[8];
    float* out = (float*)d_out;

    int B = in_sizes[0] / 784;

    size_t sm2 = K2_SMEM_FLOATS * sizeof(float);   // 47,640 B
    size_t sm3 = K3_SMEM_FLOATS * sizeof(float);   // 101,496 B
    cudaFuncSetAttribute(k2_conv,    cudaFuncAttributeMaxDynamicSharedMemorySize, (int)sm2);
    cudaFuncSetAttribute(k3_conv_fc, cudaFuncAttributeMaxDynamicSharedMemorySize, (int)sm3);

    k1_conv_pool<<<B, 256>>>(x, wb1, ws1);
    k2_conv<<<(B + K2_IMGS - 1) / K2_IMGS, 256, sm2>>>(wb2, ws2, B);
    k3_conv_fc<<<(B + K3_IMGS - 1) / K3_IMGS, 256, sm3>>>(wb3, ws3, fcw, fcb, out, B);
}

// round 2
// speedup vs baseline: 1.4723x; 1.4723x over previous
#include <cuda_runtime.h>
#include <math.h>

// ---------------- global scratch (allocation-free rule) ----------------
static __device__ float2 g_p1[4096 * 845];   // L1 pooled output as {silu, t}
static __device__ float2 g_p2[4096 * 405];   // L2 output as {silu, t}

// cubic-coefficient tables: entry (row, j) = float4(c0,c1,c2,c3), j in [0,10]
static __device__ float4 g_c1[45 * 11];
static __device__ float4 g_c2[625 * 11];
static __device__ float4 g_c3[90 * 11];
// transposed base weights, padded: wbT[f*8 + o]
static __device__ float g_wbT1[9 * 8];
static __device__ float g_wbT2[125 * 8];
static __device__ float g_wbT3[45 * 8];

__device__ __forceinline__ float silu_f(float x) {
    return __fdividef(x, 1.0f + __expf(-x));
}
// map raw value -> spline coordinate t = j + u (tap base j = floor(t))
__device__ __forceinline__ float tmap(float x) { return (x + 1.0f) * 2.5f + 3.0f; }

// ---------------- setup: build coefficient + wbT tables ----------------
__device__ __forceinline__ void coef_from_w(const float* __restrict__ ws, int row, int j,
                                            float4& c) {
    float w[4];
#pragma unroll
    for (int k = 0; k < 4; k++) {
        int g = j - 3 + k;
        w[k] = (g >= 0 && g <= 7) ? ws[row * 8 + g] : 0.0f;
    }
    const float s6 = 1.0f / 6.0f;
    c.x = (w[0] + 4.0f * w[1] + w[2]) * s6;
    c.y = (w[2] - w[0]) * 0.5f;
    c.z = (w[0] - 2.0f * w[1] + w[2]) * 0.5f;
    c.w = (-w[0] + 3.0f * w[1] - 3.0f * w[2] + w[3]) * s6;
}

__global__ void build_tables(const float* __restrict__ ws1, const float* __restrict__ ws2,
                             const float* __restrict__ ws3, const float* __restrict__ wb1,
                             const float* __restrict__ wb2, const float* __restrict__ wb3) {
    int stride = gridDim.x * blockDim.x;
    int tid = blockIdx.x * blockDim.x + threadIdx.x;
    // coef tables
    for (int i = tid; i < 45 * 11; i += stride) coef_from_w(ws1, i / 11, i % 11, g_c1[i]);
    for (int i = tid; i < 625 * 11; i += stride) coef_from_w(ws2, i / 11, i % 11, g_c2[i]);
    for (int i = tid; i < 90 * 11; i += stride) coef_from_w(ws3, i / 11, i % 11, g_c3[i]);
    // wbT padded to 8
    for (int i = tid; i < 9 * 8; i += stride) {
        int f = i / 8, o = i % 8;
        g_wbT1[i] = (o < 5) ? wb1[o * 9 + f] : 0.0f;
    }
    for (int i = tid; i < 125 * 8; i += stride) {
        int f = i / 8, o = i % 8;
        g_wbT2[i] = (o < 5) ? wb2[o * 125 + f] : 0.0f;
    }
    for (int i = tid; i < 45 * 8; i += stride) {
        int f = i / 8, o = i % 8;
        g_wbT3[i] = (o < 2) ? wb3[o * 45 + f] : 0.0f;
    }
}

// ---------------- Kernel 1: conv3(Cin=1,O=5) + maxpool2, 3 imgs/block ----------------
#define K1_IMGS 3
__global__ void __launch_bounds__(256)
k1_conv_pool(const float* __restrict__ x, int B) {
    __shared__ float4 c1s[45 * 11];
    __shared__ float2 px[K1_IMGS * 784];
    __shared__ __align__(16) float wbTs[9 * 8];
    int tid = threadIdx.x;
    int b0 = blockIdx.x * K1_IMGS;
    int nimg = min(K1_IMGS, B - b0);

    for (int i = tid; i < 45 * 11; i += 256) c1s[i] = g_c1[i];
    if (tid < 72) wbTs[tid] = g_wbT1[tid];
    for (int i = tid; i < nimg * 784; i += 256) {
        float v = x[b0 * 784 + i];
        px[i] = make_float2(silu_f(v), tmap(v));
    }
    __syncthreads();

    for (int task = tid; task < nimg * 169; task += 256) {
        int li = task / 169, p = task % 169;
        int ph = p / 13, pw = p % 13;
        float best[5];
#pragma unroll
        for (int o = 0; o < 5; o++) best[o] = -3.0e38f;

        for (int d = 0; d < 4; d++) {
            int y = 2 * ph + (d >> 1), xx = 2 * pw + (d & 1);
            float a0 = 0, a1 = 0, a2 = 0, a3 = 0, a4 = 0;
#pragma unroll
            for (int r = 0; r < 3; r++)
#pragma unroll
            for (int c = 0; c < 3; c++) {
                int f = r * 3 + c;
                float2 st = px[li * 784 + (y + r) * 28 + xx + c];
                float4 wbv = *reinterpret_cast<const float4*>(&wbTs[f * 8]);
                float wb4 = wbTs[f * 8 + 4];
                a0 += st.x * wbv.x; a1 += st.x * wbv.y; a2 += st.x * wbv.z;
                a3 += st.x * wbv.w; a4 += st.x * wb4;
                float fj = floorf(st.y);
                int j = (int)fj;
                float u = st.y - fj;
                if ((unsigned)j <= 10u) {
                    int i0 = f * 11 + j;
                    float4 q;
                    q = c1s[i0];           a0 += ((q.w * u + q.z) * u + q.y) * u + q.x;
                    q = c1s[i0 + 99];      a1 += ((q.w * u + q.z) * u + q.y) * u + q.x;
                    q = c1s[i0 + 198];     a2 += ((q.w * u + q.z) * u + q.y) * u + q.x;
                    q = c1s[i0 + 297];     a3 += ((q.w * u + q.z) * u + q.y) * u + q.x;
                    q = c1s[i0 + 396];     a4 += ((q.w * u + q.z) * u + q.y) * u + q.x;
                }
            }
            best[0] = fmaxf(best[0], a0); best[1] = fmaxf(best[1], a1);
            best[2] = fmaxf(best[2], a2); best[3] = fmaxf(best[3], a3);
            best[4] = fmaxf(best[4], a4);
        }
#pragma unroll
        for (int o = 0; o < 5; o++) {
            float v = best[o];
            g_p1[(b0 + li) * 845 + o * 169 + p] = make_float2(silu_f(v), tmap(v));
        }
    }
}

// ---------------- Kernel 2: conv5(Cin=5,O=5), 6 imgs/block, 512 thr ----------------
#define K2_IMGS 6
#define K2_SMEM ((625 * 11) * 16 + (K2_IMGS * 845) * 8 + 1000 * 4)
__global__ void __launch_bounds__(512)
k2_conv(int B) {
    extern __shared__ float4 sm4[];
    float4* c2s = sm4;                                   // 6875
    float2* in  = reinterpret_cast<float2*>(c2s + 6875); // 6*845
    float*  wbTs = reinterpret_cast<float*>(in + K2_IMGS * 845); // 1000 (16B aligned)
    int tid = threadIdx.x;
    int b0 = blockIdx.x * K2_IMGS;
    int nimg = min(K2_IMGS, B - b0);

    for (int i = tid; i < 6875; i += 512) c2s[i] = g_c2[i];
    for (int i = tid; i < 1000; i += 512) wbTs[i] = g_wbT2[i];
    for (int i = tid; i < nimg * 845; i += 512) in[i] = g_p1[b0 * 845 + i];
    __syncthreads();

    int li = tid / 81, pos = tid % 81;
    if (li >= nimg) return;
    int oy = pos / 9, ox = pos % 9;

    float a0 = 0, a1 = 0, a2 = 0, a3 = 0, a4 = 0;
    for (int c = 0; c < 5; c++) {
        const float2* inc = &in[li * 845 + c * 169];
        for (int kh = 0; kh < 5; kh++) {
            const float2* row = &inc[(oy + kh) * 13 + ox];
            int fbase = (c * 5 + kh) * 5;
#pragma unroll
            for (int kw = 0; kw < 5; kw++) {
                int f = fbase + kw;
                float2 st = row[kw];
                float4 wbv = *reinterpret_cast<const float4*>(&wbTs[f * 8]);
                float wb4 = wbTs[f * 8 + 4];
                a0 += st.x * wbv.x; a1 += st.x * wbv.y; a2 += st.x * wbv.z;
                a3 += st.x * wbv.w; a4 += st.x * wb4;
                float fj = floorf(st.y);
                int j = (int)fj;
                float u = st.y - fj;
                if ((unsigned)j <= 10u) {
                    int i0 = f * 11 + j;
                    float4 q;
                    q = c2s[i0];            a0 += ((q.w * u + q.z) * u + q.y) * u + q.x;
                    q = c2s[i0 + 1375];     a1 += ((q.w * u + q.z) * u + q.y) * u + q.x;
                    q = c2s[i0 + 2750];     a2 += ((q.w * u + q.z) * u + q.y) * u + q.x;
                    q = c2s[i0 + 4125];     a3 += ((q.w * u + q.z) * u + q.y) * u + q.x;
                    q = c2s[i0 + 5500];     a4 += ((q.w * u + q.z) * u + q.y) * u + q.x;
                }
            }
        }
    }
    int b = b0 + li;
    float acc[5] = {a0, a1, a2, a3, a4};
#pragma unroll
    for (int o = 0; o < 5; o++) {
        float v = acc[o];
        g_p2[b * 405 + o * 81 + pos] = make_float2(silu_f(v), tmap(v));
    }
}

// ---------------- Kernel 3: conv3(Cin=5,O=2) + flatten + FC, 8 imgs/block ----------------
#define K3_IMGS 8
#define K3_SMEM ((90 * 11) * 16 + (K3_IMGS * 405) * 8 + (19800 + K3_IMGS * 98 + 360 + 200) * 4)
__global__ void __launch_bounds__(256)
k3_conv_fc(const float* __restrict__ fcw, const float* __restrict__ fcb,
           float* __restrict__ out, int B) {
    extern __shared__ float4 sm4[];
    float4* c3s = sm4;                                     // 990
    float2* in  = reinterpret_cast<float2*>(c3s + 990);    // 8*405 = 3240
    float*  fw  = reinterpret_cast<float*>(in + K3_IMGS * 405); // 200*99
    float*  h   = fw + 19800;                              // 8*98
    float*  wbTs = h + K3_IMGS * 98;                       // 360
    float*  fb  = wbTs + 360;                              // 200
    int tid = threadIdx.x;
    int b0 = blockIdx.x * K3_IMGS;
    int nimg = min(K3_IMGS, B - b0);

    for (int i = tid; i < 990; i += 256) c3s[i] = g_c3[i];
    for (int i = tid; i < 360; i += 256) wbTs[i] = g_wbT3[i];
    for (int i = tid; i < 200 * 98; i += 256) fw[(i / 98) * 99 + (i % 98)] = fcw[i];
    if (tid < 200) fb[tid] = fcb[tid];
    for (int i = tid; i < nimg * 405; i += 256) in[i] = g_p2[b0 * 405 + i];
    __syncthreads();

    for (int task = tid; task < nimg * 49; task += 256) {
        int li = task / 49, pos = task % 49;
        int oy = pos / 7, ox = pos % 7;
        float a0 = 0, a1 = 0;
        for (int c = 0; c < 5; c++) {
#pragma unroll
            for (int kh = 0; kh < 3; kh++)
#pragma unroll
            for (int kw = 0; kw < 3; kw++) {
                int f = (c * 3 + kh) * 3 + kw;
                float2 st = in[li * 405 + c * 81 + (oy + kh) * 9 + ox + kw];
                a0 += st.x * wbTs[f * 8 + 0];
                a1 += st.x * wbTs[f * 8 + 1];
                float fj = floorf(st.y);
                int j = (int)fj;
                float u = st.y - fj;
                if ((unsigned)j <= 10u) {
                    int i0 = f * 11 + j;
                    float4 q;
                    q = c3s[i0];        a0 += ((q.w * u + q.z) * u + q.y) * u + q.x;
                    q = c3s[i0 + 495];  a1 += ((q.w * u + q.z) * u + q.y) * u + q.x;
                }
            }
        }
        h[li * 98 + pos]      = a0;
        h[li * 98 + 49 + pos] = a1;
    }
    __syncthreads();

    for (int task = tid; task < nimg * 200; task += 256) {
        int li = task / 200, o = task % 200;
        float acc = fb[o];
        const float* hr = &h[li * 98];
        const float* wr = &fw[o * 99];
#pragma unroll 7
        for (int i = 0; i < 98; i++) acc += hr[i] * wr[i];
        out[(b0 + li) * 200 + o] = acc;
    }
}

extern "C" void kernel_launch(void* const* d_in, const int* in_sizes, int n_in,
                              void* d_out, int out_size) {
    const float* x   = (const float*)d_in[0];
    const float* wb1 = (const float*)d_in[1];
    const float* ws1 = (const float*)d_in[2];
    const float* wb2 = (const float*)d_in[3];
    const float* ws2 = (const float*)d_in[4];
    const float* wb3 = (const float*)d_in[5];
    const float* ws3 = (const float*)d_in[6];
    const float* fcw = (const float*)d_in[7];
    const float* fcb = (const float*)d_in[8];
    float* out = (float*)d_out;

    int B = in_sizes[0] / 784;

    static int configured = -1;
    if (configured < 0) {
        cudaFuncSetAttribute(k2_conv, cudaFuncAttributeMaxDynamicSharedMemorySize, K2_SMEM);
        cudaFuncSetAttribute(k3_conv_fc, cudaFuncAttributeMaxDynamicSharedMemorySize, K3_SMEM);
        configured = 1;
    }

    build_tables<<<32, 256>>>(ws1, ws2, ws3, wb1, wb2, wb3);
    k1_conv_pool<<<(B + K1_IMGS - 1) / K1_IMGS, 256>>>(x, B);
    k2_conv<<<(B + K2_IMGS - 1) / K2_IMGS, 512, K2_SMEM>>>(B);
    k3_conv_fc<<<(B + K3_IMGS - 1) / K3_IMGS, 256, K3_SMEM>>>(fcw, fcb, out, B);
}

// round 4
// speedup vs baseline: 2.2550x; 1.5316x over previous
#include <cuda_runtime.h>
#include <cuda_fp16.h>
#include <math.h>

// ---------------- global scratch (allocation-free rule) ----------------
static __device__ float2 g_p1[4096 * 845];   // L1 pooled output as {silu, t}
static __device__ float2 g_p2[4096 * 405];   // L2 output as {silu, t}

// fp16 cubic-coefficient tables: entry (row, j) = 4 halves {c0,c1,c2,c3}, j in [0,10]
static __device__ uint2 g_c1[45 * 11];
static __device__ uint2 g_c2[625 * 11];
static __device__ uint2 g_c3[90 * 11];
// transposed base weights (fp32), padded: wbT[f*8 + o]
static __device__ float g_wbT1[9 * 8];
static __device__ float g_wbT2[125 * 8];
static __device__ float g_wbT3[45 * 8];

__device__ __forceinline__ float silu_f(float x) {
    return __fdividef(x, 1.0f + __expf(-x));
}
// map raw value -> spline coordinate t = j + u (tap base j = floor(t))
__device__ __forceinline__ float tmap(float x) { return (x + 1.0f) * 2.5f + 3.0f; }

// evaluate cubic from packed fp16 coefs
__device__ __forceinline__ float cubic_h(uint2 q, float u) {
    float2 c01 = __half22float2(*reinterpret_cast<const __half2*>(&q.x));
    float2 c23 = __half22float2(*reinterpret_cast<const __half2*>(&q.y));
    return ((c23.y * u + c23.x) * u + c01.y) * u + c01.x;
}

// ---------------- setup: build coefficient + wbT tables ----------------
__device__ __forceinline__ uint2 coef_from_w(const float* __restrict__ ws, int row, int j) {
    float w[4];
#pragma unroll
    for (int k = 0; k < 4; k++) {
        int g = j - 3 + k;
        w[k] = (g >= 0 && g <= 7) ? ws[row * 8 + g] : 0.0f;
    }
    const float s6 = 1.0f / 6.0f;
    float c0 = (w[0] + 4.0f * w[1] + w[2]) * s6;
    float c1 = (w[2] - w[0]) * 0.5f;
    float c2 = (w[0] - 2.0f * w[1] + w[2]) * 0.5f;
    float c3 = (-w[0] + 3.0f * w[1] - 3.0f * w[2] + w[3]) * s6;
    uint2 r;
    __half2 h01 = __floats2half2_rn(c0, c1);
    __half2 h23 = __floats2half2_rn(c2, c3);
    r.x = *reinterpret_cast<unsigned*>(&h01);
    r.y = *reinterpret_cast<unsigned*>(&h23);
    return r;
}

__global__ void build_tables(const float* __restrict__ ws1, const float* __restrict__ ws2,
                             const float* __restrict__ ws3, const float* __restrict__ wb1,
                             const float* __restrict__ wb2, const float* __restrict__ wb3) {
    int stride = gridDim.x * blockDim.x;
    int tid = blockIdx.x * blockDim.x + threadIdx.x;
    for (int i = tid; i < 45 * 11; i += stride) g_c1[i] = coef_from_w(ws1, i / 11, i % 11);
    for (int i = tid; i < 625 * 11; i += stride) g_c2[i] = coef_from_w(ws2, i / 11, i % 11);
    for (int i = tid; i < 90 * 11; i += stride) g_c3[i] = coef_from_w(ws3, i / 11, i % 11);
    for (int i = tid; i < 9 * 8; i += stride) {
        int f = i / 8, o = i % 8;
        g_wbT1[i] = (o < 5) ? wb1[o * 9 + f] : 0.0f;
    }
    for (int i = tid; i < 125 * 8; i += stride) {
        int f = i / 8, o = i % 8;
        g_wbT2[i] = (o < 5) ? wb2[o * 125 + f] : 0.0f;
    }
    for (int i = tid; i < 45 * 8; i += stride) {
        int f = i / 8, o = i % 8;
        g_wbT3[i] = (o < 2) ? wb3[o * 45 + f] : 0.0f;
    }
}

// ---------------- Kernel 1: conv3(Cin=1,O=5) + maxpool2, 3 imgs/block ----------------
#define K1_IMGS 3
__global__ void __launch_bounds__(256)
k1_conv_pool(const float* __restrict__ x, int B) {
    __shared__ __align__(16) float wbTs[9 * 8];
    __shared__ uint2 c1s[45 * 11];
    __shared__ float2 px[K1_IMGS * 784];
    int tid = threadIdx.x;
    int b0 = blockIdx.x * K1_IMGS;
    int nimg = min(K1_IMGS, B - b0);

    for (int i = tid; i < 45 * 11; i += 256) c1s[i] = g_c1[i];
    if (tid < 72) wbTs[tid] = g_wbT1[tid];
    for (int i = tid; i < nimg * 784; i += 256) {
        float v = x[b0 * 784 + i];
        px[i] = make_float2(silu_f(v), tmap(v));
    }
    __syncthreads();

    for (int task = tid; task < nimg * 169; task += 256) {
        int li = task / 169, p = task % 169;
        int ph = p / 13, pw = p % 13;
        float best[5];
#pragma unroll
        for (int o = 0; o < 5; o++) best[o] = -3.0e38f;

        for (int d = 0; d < 4; d++) {
            int y = 2 * ph + (d >> 1), xx = 2 * pw + (d & 1);
            float a0 = 0, a1 = 0, a2 = 0, a3 = 0, a4 = 0;
#pragma unroll
            for (int r = 0; r < 3; r++)
#pragma unroll
            for (int c = 0; c < 3; c++) {
                int f = r * 3 + c;
                float2 st = px[li * 784 + (y + r) * 28 + xx + c];
                float4 wbv = *reinterpret_cast<const float4*>(&wbTs[f * 8]);
                float wb4 = wbTs[f * 8 + 4];
                a0 += st.x * wbv.x; a1 += st.x * wbv.y; a2 += st.x * wbv.z;
                a3 += st.x * wbv.w; a4 += st.x * wb4;
                float fj = floorf(st.y);
                int j = (int)fj;
                float u = st.y - fj;
                if ((unsigned)j <= 10u) {
                    int i0 = f * 11 + j;
                    a0 += cubic_h(c1s[i0], u);
                    a1 += cubic_h(c1s[i0 + 99], u);
                    a2 += cubic_h(c1s[i0 + 198], u);
                    a3 += cubic_h(c1s[i0 + 297], u);
                    a4 += cubic_h(c1s[i0 + 396], u);
                }
            }
            best[0] = fmaxf(best[0], a0); best[1] = fmaxf(best[1], a1);
            best[2] = fmaxf(best[2], a2); best[3] = fmaxf(best[3], a3);
            best[4] = fmaxf(best[4], a4);
        }
#pragma unroll
        for (int o = 0; o < 5; o++) {
            float v = best[o];
            g_p1[(b0 + li) * 845 + o * 169 + p] = make_float2(silu_f(v), tmap(v));
        }
    }
}

// ---------------- Kernel 2: conv5(Cin=5,O=5), 6 imgs/block, 512 thr, 2 blk/SM ----------------
// smem layout (bytes): wbTs [0, 4000) 16-aligned for LDS.128; c2s [4000, 59000);
// in (float2, 8B-aligned) [59000, 99560)
#define K2_IMGS 6
#define K2_SMEM (4000 + 6875 * 8 + K2_IMGS * 845 * 8)
__global__ void __launch_bounds__(512, 2)
k2_conv(int B) {
    extern __shared__ __align__(16) char smraw[];
    float* wbTs = reinterpret_cast<float*>(smraw);                 // 1000 floats
    uint2* c2s  = reinterpret_cast<uint2*>(smraw + 4000);          // 6875
    float2* in  = reinterpret_cast<float2*>(smraw + 4000 + 6875 * 8); // 6*845
    int tid = threadIdx.x;
    int b0 = blockIdx.x * K2_IMGS;
    int nimg = min(K2_IMGS, B - b0);

    for (int i = tid; i < 6875; i += 512) c2s[i] = g_c2[i];
    for (int i = tid; i < 1000; i += 512) wbTs[i] = g_wbT2[i];
    for (int i = tid; i < nimg * 845; i += 512) in[i] = g_p1[b0 * 845 + i];
    __syncthreads();

    int li = tid / 81, pos = tid % 81;
    if (li >= nimg) return;
    int oy = pos / 9, ox = pos % 9;

    float a0 = 0, a1 = 0, a2 = 0, a3 = 0, a4 = 0;
    for (int c = 0; c < 5; c++) {
        const float2* inc = &in[li * 845 + c * 169];
        for (int kh = 0; kh < 5; kh++) {
            const float2* row = &inc[(oy + kh) * 13 + ox];
            int fbase = (c * 5 + kh) * 5;
#pragma unroll
            for (int kw = 0; kw < 5; kw++) {
                int f = fbase + kw;
                float2 st = row[kw];
                float4 wbv = *reinterpret_cast<const float4*>(&wbTs[f * 8]);
                float wb4 = wbTs[f * 8 + 4];
                a0 += st.x * wbv.x; a1 += st.x * wbv.y; a2 += st.x * wbv.z;
                a3 += st.x * wbv.w; a4 += st.x * wb4;
                float fj = floorf(st.y);
                int j = (int)fj;
                float u = st.y - fj;
                if ((unsigned)j <= 10u) {
                    int i0 = f * 11 + j;
                    a0 += cubic_h(c2s[i0], u);
                    a1 += cubic_h(c2s[i0 + 1375], u);
                    a2 += cubic_h(c2s[i0 + 2750], u);
                    a3 += cubic_h(c2s[i0 + 4125], u);
                    a4 += cubic_h(c2s[i0 + 5500], u);
                }
            }
        }
    }
    int b = b0 + li;
    float acc[5] = {a0, a1, a2, a3, a4};
#pragma unroll
    for (int o = 0; o < 5; o++) {
        float v = acc[o];
        g_p2[b * 405 + o * 81 + pos] = make_float2(silu_f(v), tmap(v));
    }
}

// ---------------- Kernel 3: conv3(Cin=5,O=2) + flatten + FC, 16 imgs/block ----------------
// smem layout (bytes): c3s [0, 7920); in [7920, 59760); fw/h/wbTs/fb after (scalar access only)
#define K3_IMGS 16
#define K3_SMEM (990 * 8 + K3_IMGS * 405 * 8 + (19800 + K3_IMGS * 98 + 360 + 200) * 4)
__global__ void __launch_bounds__(512)
k3_conv_fc(const float* __restrict__ fcw, const float* __restrict__ fcb,
           float* __restrict__ out, int B) {
    extern __shared__ __align__(16) char smraw3[];
    uint2* c3s = reinterpret_cast<uint2*>(smraw3);             // 990
    float2* in = reinterpret_cast<float2*>(smraw3 + 990 * 8);  // 16*405
    float* fw  = reinterpret_cast<float*>(smraw3 + 990 * 8 + K3_IMGS * 405 * 8); // 200*99
    float* h   = fw + 19800;                                   // 16*98
    float* wbTs = h + K3_IMGS * 98;                            // 360
    float* fb  = wbTs + 360;                                   // 200
    int tid = threadIdx.x;
    int b0 = blockIdx.x * K3_IMGS;
    int nimg = min(K3_IMGS, B - b0);

    for (int i = tid; i < 990; i += 512) c3s[i] = g_c3[i];
    for (int i = tid; i < 360; i += 512) wbTs[i] = g_wbT3[i];
    for (int i = tid; i < 200 * 98; i += 512) fw[(i / 98) * 99 + (i % 98)] = fcw[i];
    if (tid < 200) fb[tid] = fcb[tid];
    for (int i = tid; i < nimg * 405; i += 512) in[i] = g_p2[b0 * 405 + i];
    __syncthreads();

    for (int task = tid; task < nimg * 49; task += 512) {
        int li = task / 49, pos = task % 49;
        int oy = pos / 7, ox = pos % 7;
        float a0 = 0, a1 = 0;
        for (int c = 0; c < 5; c++) {
#pragma unroll
            for (int kh = 0; kh < 3; kh++)
#pragma unroll
            for (int kw = 0; kw < 3; kw++) {
                int f = (c * 3 + kh) * 3 + kw;
                float2 st = in[li * 405 + c * 81 + (oy + kh) * 9 + ox + kw];
                a0 += st.x * wbTs[f * 8 + 0];
                a1 += st.x * wbTs[f * 8 + 1];
                float fj = floorf(st.y);
                int j = (int)fj;
                float u = st.y - fj;
                if ((unsigned)j <= 10u) {
                    int i0 = f * 11 + j;
                    a0 += cubic_h(c3s[i0], u);
                    a1 += cubic_h(c3s[i0 + 495], u);
                }
            }
        }
        h[li * 98 + pos]      = a0;
        h[li * 98 + 49 + pos] = a1;
    }
    __syncthreads();

    for (int task = tid; task < nimg * 200; task += 512) {
        int li = task / 200, o = task % 200;
        float acc = fb[o];
        const float* hr = &h[li * 98];
        const float* wr = &fw[o * 99];
#pragma unroll 7
        for (int i = 0; i < 98; i++) acc += hr[i] * wr[i];
        out[(b0 + li) * 200 + o] = acc;
    }
}

extern "C" void kernel_launch(void* const* d_in, const int* in_sizes, int n_in,
                              void* d_out, int out_size) {
    const float* x   = (const float*)d_in[0];
    const float* wb1 = (const float*)d_in[1];
    const float* ws1 = (const float*)d_in[2];
    const float* wb2 = (const float*)d_in[3];
    const float* ws2 = (const float*)d_in[4];
    const float* wb3 = (const float*)d_in[5];
    const float* ws3 = (const float*)d_in[6];
    const float* fcw = (const float*)d_in[7];
    const float* fcb = (const float*)d_in[8];
    float* out = (float*)d_out;

    int B = in_sizes[0] / 784;

    static int configured = -1;
    if (configured < 0) {
        cudaFuncSetAttribute(k2_conv, cudaFuncAttributeMaxDynamicSharedMemorySize, K2_SMEM);
        cudaFuncSetAttribute(k3_conv_fc, cudaFuncAttributeMaxDynamicSharedMemorySize, K3_SMEM);
        configured = 1;
    }

    build_tables<<<32, 256>>>(ws1, ws2, ws3, wb1, wb2, wb3);
    k1_conv_pool<<<(B + K1_IMGS - 1) / K1_IMGS, 256>>>(x, B);
    k2_conv<<<(B + K2_IMGS - 1) / K2_IMGS, 512, K2_SMEM>>>(B);
    k3_conv_fc<<<(B + K3_IMGS - 1) / K3_IMGS, 512, K3_SMEM>>>(fcw, fcb, out, B);
}